// round 7
// baseline (speedup 1.0000x reference)
#include <cuda_runtime.h>
#include <cuda_bf16.h>

#define N_NODES 8192
#define NFEAT   256
#define NHID    64
#define NHEADS  4
#define NCLASS  121
#define MAXDEG  256
#define ALPHA_LRELU 0.2f

// ---------------- scratch (static device globals; no allocation) ----------------
__device__ int   g_deg[N_NODES];
__device__ int   g_nbr[N_NODES * MAXDEG];
__device__ float g_Wh [N_NODES * 256];        // layer-1 Wh, all 4 heads concatenated
__device__ float g_fsrc[N_NODES * NHEADS];    // interleaved [node][head]
__device__ float g_fdst[N_NODES * NHEADS];    // interleaved [node][head]
__device__ float g_hcat[N_NODES * 256];
__device__ float g_Wh2[N_NODES * 128];        // layer-2 Wh, padded to 128 cols
__device__ float g_f2srcp[2][N_NODES];        // layer-2 score partials (per col-block)
__device__ float g_f2dstp[2][N_NODES];

// ------- CSR build: warp per row, ballot compaction, 4-deep load batching -------
__global__ __launch_bounds__(256) void build_csr(const float* __restrict__ adj) {
    int warp = (blockIdx.x * blockDim.x + threadIdx.x) >> 5;
    int lane = threadIdx.x & 31;
    if (warp >= N_NODES) return;
    const float4* row = reinterpret_cast<const float4*>(adj + (size_t)warp * N_NODES);
    int cnt = 0;
    int* out = g_nbr + warp * MAXDEG;
    // 2048 float4 per row; 4 batches of 32 lanes per outer iter -> 16 outer iters
    for (int base = 0; base < N_NODES / 4; base += 128) {
        float4 v[4];
        #pragma unroll
        for (int r = 0; r < 4; r++) v[r] = row[base + r * 32 + lane];   // 4 loads in flight
        #pragma unroll
        for (int r = 0; r < 4; r++) {
            float vv[4] = {v[r].x, v[r].y, v[r].z, v[r].w};
            int col0 = (base + r * 32 + lane) * 4;
            #pragma unroll
            for (int q = 0; q < 4; q++) {
                unsigned m = __ballot_sync(0xffffffffu, vv[q] > 0.0f);
                if (vv[q] > 0.0f) {
                    int pos = cnt + __popc(m & ((1u << lane) - 1u));
                    if (pos < MAXDEG) out[pos] = col0 + q;
                }
                cnt += __popc(m);
            }
        }
    }
    if (lane == 0) g_deg[warp] = cnt < MAXDEG ? cnt : MAXDEG;
}

// ------- tiled fp32 GEMM: BM=64, BN=64, BK=16, 256 thr, 4x4 microtile -----------
// MODE 0: B(k,c) = Ws[(c>>6)*NFEAT*NHID + k*NHID + (c&63)]; epilogue computes
//         f_src/f_dst for this head (BN == NHID) via in-register dot + shuffle.
// MODE 1: B(k,c) = (c<NCLASS) ? W_out[k*NCLASS + c] : 0; epilogue computes
//         partial f2 scores for this 64-col block into g_f2{src,dst}p[bx].
template <int MODE>
__global__ __launch_bounds__(256) void sgemm4(const float* __restrict__ A,
                                              const float* __restrict__ B,
                                              const float* __restrict__ avec,
                                              float* __restrict__ C, int ldc) {
    __shared__ float sA[16][68];    // transposed A tile [k][m]
    __shared__ float sB[16][68];    // B tile [k][c]

    int tid = threadIdx.x;
    int m0 = blockIdx.y * 64;
    int c0 = blockIdx.x * 64;

    int ar  = tid >> 2;            // 0..63
    int ac4 = (tid & 3) * 4;       // 0,4,8,12
    int bk  = tid >> 4;            // 0..15
    int bc4 = (tid & 15) * 4;      // 0..60

    int ty = tid >> 4;             // 0..15 -> rows ty*4..+3
    int tx = tid & 15;             // 0..15 -> cols tx*4..+3

    float acc[4][4];
    #pragma unroll
    for (int i = 0; i < 4; i++)
        #pragma unroll
        for (int j = 0; j < 4; j++) acc[i][j] = 0.0f;

    for (int k0 = 0; k0 < NFEAT; k0 += 16) {
        float4 av = *reinterpret_cast<const float4*>(A + (size_t)(m0 + ar) * NFEAT + k0 + ac4);
        sA[ac4 + 0][ar] = av.x;
        sA[ac4 + 1][ar] = av.y;
        sA[ac4 + 2][ar] = av.z;
        sA[ac4 + 3][ar] = av.w;
        if (MODE == 0) {
            const float* bp = B + (size_t)(c0 >> 6) * (NFEAT * NHID)
                                + (size_t)(k0 + bk) * NHID + bc4;
            float4 bv = *reinterpret_cast<const float4*>(bp);
            sB[bk][bc4 + 0] = bv.x;
            sB[bk][bc4 + 1] = bv.y;
            sB[bk][bc4 + 2] = bv.z;
            sB[bk][bc4 + 3] = bv.w;
        } else {
            #pragma unroll
            for (int j = 0; j < 4; j++) {
                int c = c0 + bc4 + j;
                sB[bk][bc4 + j] = (c < NCLASS) ? B[(size_t)(k0 + bk) * NCLASS + c] : 0.0f;
            }
        }
        __syncthreads();

        #pragma unroll
        for (int kk = 0; kk < 16; kk++) {
            float4 a4 = *reinterpret_cast<const float4*>(&sA[kk][ty * 4]);
            float4 b4 = *reinterpret_cast<const float4*>(&sB[kk][tx * 4]);
            float a[4] = {a4.x, a4.y, a4.z, a4.w};
            float b[4] = {b4.x, b4.y, b4.z, b4.w};
            #pragma unroll
            for (int i = 0; i < 4; i++)
                #pragma unroll
                for (int j = 0; j < 4; j++) acc[i][j] = fmaf(a[i], b[j], acc[i][j]);
        }
        __syncthreads();
    }

    #pragma unroll
    for (int i = 0; i < 4; i++) {
        float4 v = make_float4(acc[i][0], acc[i][1], acc[i][2], acc[i][3]);
        *reinterpret_cast<float4*>(C + (size_t)(m0 + ty * 4 + i) * ldc + c0 + tx * 4) = v;
    }

    // -------- fused attention-score epilogue --------
    float as[4], ad[4];
    if (MODE == 0) {
        const float* ah = avec + (c0 >> 6) * (2 * NHID);   // this head's a-vector
        #pragma unroll
        for (int j = 0; j < 4; j++) {
            as[j] = ah[tx * 4 + j];
            ad[j] = ah[NHID + tx * 4 + j];
        }
    } else {
        #pragma unroll
        for (int j = 0; j < 4; j++) {
            int c = c0 + tx * 4 + j;
            as[j] = (c < NCLASS) ? avec[c] : 0.0f;
            ad[j] = (c < NCLASS) ? avec[NCLASS + c] : 0.0f;
        }
    }
    #pragma unroll
    for (int i = 0; i < 4; i++) {
        float s = fmaf(acc[i][0], as[0], acc[i][1] * as[1]) +
                  fmaf(acc[i][2], as[2], acc[i][3] * as[3]);
        float d = fmaf(acc[i][0], ad[0], acc[i][1] * ad[1]) +
                  fmaf(acc[i][2], ad[2], acc[i][3] * ad[3]);
        #pragma unroll
        for (int o = 1; o < 16; o <<= 1) {
            s += __shfl_xor_sync(0xffffffffu, s, o);
            d += __shfl_xor_sync(0xffffffffu, d, o);
        }
        if (tx == 0) {
            int row = m0 + ty * 4 + i;
            if (MODE == 0) {
                int h = c0 >> 6;
                g_fsrc[row * 4 + h] = s;
                g_fdst[row * 4 + h] = d;
            } else {
                g_f2srcp[blockIdx.x][row] = s;
                g_f2dstp[blockIdx.x][row] = d;
            }
        }
    }
}

// ---------------- layer-1 sparse attention + aggregate + ELU (4 nodes/block) ----
__global__ __launch_bounds__(256) void layer1_agg() {
    __shared__ int   s_nbr[4][MAXDEG];
    __shared__ float s_w[4][NHEADS][MAXDEG];
    __shared__ float s_red[4][NHEADS][2];

    int tid  = threadIdx.x;
    int g    = tid >> 6;          // group 0..3
    int lt   = tid & 63;          // lane in group
    int wig  = lt >> 5;           // warp in group 0..1
    int lane = tid & 31;

    int i   = blockIdx.x * 4 + g;
    int deg = g_deg[i];

    for (int t = lt; t < deg; t += 64) s_nbr[g][t] = g_nbr[i * MAXDEG + t];
    __syncthreads();

    float4 fs = *reinterpret_cast<const float4*>(g_fsrc + (size_t)i * 4);
    float fsrcA[4] = {fs.x, fs.y, fs.z, fs.w};

    float lmax[4] = {-1e30f, -1e30f, -1e30f, -1e30f};
    for (int j = lt; j < deg; j += 64) {
        float4 fd = *reinterpret_cast<const float4*>(g_fdst + (size_t)s_nbr[g][j] * 4);
        float fdA[4] = {fd.x, fd.y, fd.z, fd.w};
        #pragma unroll
        for (int h = 0; h < 4; h++) {
            float e = fsrcA[h] + fdA[h];
            e = e >= 0.0f ? e : ALPHA_LRELU * e;
            s_w[g][h][j] = e;
            lmax[h] = fmaxf(lmax[h], e);
        }
    }
    #pragma unroll
    for (int h = 0; h < 4; h++) {
        #pragma unroll
        for (int o = 16; o; o >>= 1) lmax[h] = fmaxf(lmax[h], __shfl_xor_sync(0xffffffffu, lmax[h], o));
        if (lane == 0) s_red[g][h][wig] = lmax[h];
    }
    __syncthreads();
    float m[4];
    #pragma unroll
    for (int h = 0; h < 4; h++) m[h] = fmaxf(s_red[g][h][0], s_red[g][h][1]);

    float lsum[4] = {0.0f, 0.0f, 0.0f, 0.0f};
    for (int j = lt; j < deg; j += 64) {
        #pragma unroll
        for (int h = 0; h < 4; h++) {
            float w = __expf(s_w[g][h][j] - m[h]);
            s_w[g][h][j] = w;
            lsum[h] += w;
        }
    }
    __syncthreads();   // protect s_red reuse
    #pragma unroll
    for (int h = 0; h < 4; h++) {
        #pragma unroll
        for (int o = 16; o; o >>= 1) lsum[h] += __shfl_xor_sync(0xffffffffu, lsum[h], o);
        if (lane == 0) s_red[g][h][wig] = lsum[h];
    }
    __syncthreads();

    // gather: thread lt covers cols 4*lt..4*lt+3 (head h2 = lt>>4), 8-deep MLP
    int h2 = lt >> 4;
    float inv = 1.0f / (s_red[g][h2][0] + s_red[g][h2][1]);
    const float4* wh4 = reinterpret_cast<const float4*>(g_Wh);
    const float* wrow = s_w[g][h2];
    const int*   nrow = s_nbr[g];

    float4 acc0 = make_float4(0.f, 0.f, 0.f, 0.f);
    float4 acc1 = make_float4(0.f, 0.f, 0.f, 0.f);
    int j = 0;
    for (; j + 7 < deg; j += 8) {
        float w0 = wrow[j],     w1 = wrow[j + 1], w2 = wrow[j + 2], w3 = wrow[j + 3];
        float w4 = wrow[j + 4], w5 = wrow[j + 5], w6 = wrow[j + 6], w7 = wrow[j + 7];
        float4 v0 = wh4[(size_t)nrow[j]     * 64 + lt];
        float4 v1 = wh4[(size_t)nrow[j + 1] * 64 + lt];
        float4 v2 = wh4[(size_t)nrow[j + 2] * 64 + lt];
        float4 v3 = wh4[(size_t)nrow[j + 3] * 64 + lt];
        float4 v4 = wh4[(size_t)nrow[j + 4] * 64 + lt];
        float4 v5 = wh4[(size_t)nrow[j + 5] * 64 + lt];
        float4 v6 = wh4[(size_t)nrow[j + 6] * 64 + lt];
        float4 v7 = wh4[(size_t)nrow[j + 7] * 64 + lt];
        acc0.x = fmaf(w0, v0.x, acc0.x); acc0.y = fmaf(w0, v0.y, acc0.y);
        acc0.z = fmaf(w0, v0.z, acc0.z); acc0.w = fmaf(w0, v0.w, acc0.w);
        acc1.x = fmaf(w1, v1.x, acc1.x); acc1.y = fmaf(w1, v1.y, acc1.y);
        acc1.z = fmaf(w1, v1.z, acc1.z); acc1.w = fmaf(w1, v1.w, acc1.w);
        acc0.x = fmaf(w2, v2.x, acc0.x); acc0.y = fmaf(w2, v2.y, acc0.y);
        acc0.z = fmaf(w2, v2.z, acc0.z); acc0.w = fmaf(w2, v2.w, acc0.w);
        acc1.x = fmaf(w3, v3.x, acc1.x); acc1.y = fmaf(w3, v3.y, acc1.y);
        acc1.z = fmaf(w3, v3.z, acc1.z); acc1.w = fmaf(w3, v3.w, acc1.w);
        acc0.x = fmaf(w4, v4.x, acc0.x); acc0.y = fmaf(w4, v4.y, acc0.y);
        acc0.z = fmaf(w4, v4.z, acc0.z); acc0.w = fmaf(w4, v4.w, acc0.w);
        acc1.x = fmaf(w5, v5.x, acc1.x); acc1.y = fmaf(w5, v5.y, acc1.y);
        acc1.z = fmaf(w5, v5.z, acc1.z); acc1.w = fmaf(w5, v5.w, acc1.w);
        acc0.x = fmaf(w6, v6.x, acc0.x); acc0.y = fmaf(w6, v6.y, acc0.y);
        acc0.z = fmaf(w6, v6.z, acc0.z); acc0.w = fmaf(w6, v6.w, acc0.w);
        acc1.x = fmaf(w7, v7.x, acc1.x); acc1.y = fmaf(w7, v7.y, acc1.y);
        acc1.z = fmaf(w7, v7.z, acc1.z); acc1.w = fmaf(w7, v7.w, acc1.w);
    }
    for (; j < deg; j++) {
        float w0 = wrow[j];
        float4 v0 = wh4[(size_t)nrow[j] * 64 + lt];
        acc0.x = fmaf(w0, v0.x, acc0.x); acc0.y = fmaf(w0, v0.y, acc0.y);
        acc0.z = fmaf(w0, v0.z, acc0.z); acc0.w = fmaf(w0, v0.w, acc0.w);
    }
    float4 r;
    r.x = (acc0.x + acc1.x) * inv;
    r.y = (acc0.y + acc1.y) * inv;
    r.z = (acc0.z + acc1.z) * inv;
    r.w = (acc0.w + acc1.w) * inv;
    r.x = r.x > 0.0f ? r.x : expm1f(r.x);
    r.y = r.y > 0.0f ? r.y : expm1f(r.y);
    r.z = r.z > 0.0f ? r.z : expm1f(r.z);
    r.w = r.w > 0.0f ? r.w : expm1f(r.w);
    reinterpret_cast<float4*>(g_hcat)[(size_t)i * 64 + lt] = r;
}

// ---------------- layer-2 sparse attention + aggregate (4 nodes/block) ----------
__global__ __launch_bounds__(256) void layer2_agg(float* __restrict__ out) {
    __shared__ int   s_nbr[4][MAXDEG];
    __shared__ float s_w[4][MAXDEG];
    __shared__ float s_red[4][2];

    int tid  = threadIdx.x;
    int g    = tid >> 6;
    int lt   = tid & 63;
    int wig  = lt >> 5;
    int lane = tid & 31;

    int i   = blockIdx.x * 4 + g;
    int deg = g_deg[i];

    for (int t = lt; t < deg; t += 64) s_nbr[g][t] = g_nbr[i * MAXDEG + t];
    __syncthreads();

    float fsrc = g_f2srcp[0][i] + g_f2srcp[1][i];
    float lmax = -1e30f;
    for (int j = lt; j < deg; j += 64) {
        int nb = s_nbr[g][j];
        float e = fsrc + g_f2dstp[0][nb] + g_f2dstp[1][nb];
        e = e >= 0.0f ? e : ALPHA_LRELU * e;
        s_w[g][j] = e;
        lmax = fmaxf(lmax, e);
    }
    #pragma unroll
    for (int o = 16; o; o >>= 1) lmax = fmaxf(lmax, __shfl_xor_sync(0xffffffffu, lmax, o));
    if (lane == 0) s_red[g][wig] = lmax;
    __syncthreads();
    float m = fmaxf(s_red[g][0], s_red[g][1]);

    float lsum = 0.0f;
    for (int j = lt; j < deg; j += 64) {
        float w = __expf(s_w[g][j] - m);
        s_w[g][j] = w;
        lsum += w;
    }
    __syncthreads();
    #pragma unroll
    for (int o = 16; o; o >>= 1) lsum += __shfl_xor_sync(0xffffffffu, lsum, o);
    if (lane == 0) s_red[g][wig] = lsum;
    __syncthreads();
    float inv = 1.0f / (s_red[g][0] + s_red[g][1]);

    // gather: thread lt covers cols 2*lt, 2*lt+1 via float2, 8-deep MLP
    const float2* wh2 = reinterpret_cast<const float2*>(g_Wh2);
    const float*  wrow = s_w[g];
    const int*    nrow = s_nbr[g];
    float2 acc0 = make_float2(0.f, 0.f);
    float2 acc1 = make_float2(0.f, 0.f);
    int j = 0;
    for (; j + 7 < deg; j += 8) {
        float w0 = wrow[j],     w1 = wrow[j + 1], w2 = wrow[j + 2], w3 = wrow[j + 3];
        float w4 = wrow[j + 4], w5 = wrow[j + 5], w6 = wrow[j + 6], w7 = wrow[j + 7];
        float2 v0 = wh2[(size_t)nrow[j]     * 64 + lt];
        float2 v1 = wh2[(size_t)nrow[j + 1] * 64 + lt];
        float2 v2 = wh2[(size_t)nrow[j + 2] * 64 + lt];
        float2 v3 = wh2[(size_t)nrow[j + 3] * 64 + lt];
        float2 v4 = wh2[(size_t)nrow[j + 4] * 64 + lt];
        float2 v5 = wh2[(size_t)nrow[j + 5] * 64 + lt];
        float2 v6 = wh2[(size_t)nrow[j + 6] * 64 + lt];
        float2 v7 = wh2[(size_t)nrow[j + 7] * 64 + lt];
        acc0.x = fmaf(w0, v0.x, acc0.x); acc0.y = fmaf(w0, v0.y, acc0.y);
        acc1.x = fmaf(w1, v1.x, acc1.x); acc1.y = fmaf(w1, v1.y, acc1.y);
        acc0.x = fmaf(w2, v2.x, acc0.x); acc0.y = fmaf(w2, v2.y, acc0.y);
        acc1.x = fmaf(w3, v3.x, acc1.x); acc1.y = fmaf(w3, v3.y, acc1.y);
        acc0.x = fmaf(w4, v4.x, acc0.x); acc0.y = fmaf(w4, v4.y, acc0.y);
        acc1.x = fmaf(w5, v5.x, acc1.x); acc1.y = fmaf(w5, v5.y, acc1.y);
        acc0.x = fmaf(w6, v6.x, acc0.x); acc0.y = fmaf(w6, v6.y, acc0.y);
        acc1.x = fmaf(w7, v7.x, acc1.x); acc1.y = fmaf(w7, v7.y, acc1.y);
    }
    for (; j < deg; j++) {
        float w0 = wrow[j];
        float2 v0 = wh2[(size_t)nrow[j] * 64 + lt];
        acc0.x = fmaf(w0, v0.x, acc0.x); acc0.y = fmaf(w0, v0.y, acc0.y);
    }
    int c = lt * 2;
    if (c < NCLASS)     out[(size_t)i * NCLASS + c]     = (acc0.x + acc1.x) * inv;
    if (c + 1 < NCLASS) out[(size_t)i * NCLASS + c + 1] = (acc0.y + acc1.y) * inv;
}

// ---------------- host launch ---------------------------------------------------
extern "C" void kernel_launch(void* const* d_in, const int* in_sizes, int n_in,
                              void* d_out, int out_size) {
    const float* x       = (const float*)d_in[0];   // [8192, 256]
    const float* adj     = (const float*)d_in[1];   // [8192, 8192]
    const float* Ws      = (const float*)d_in[2];   // [4, 256, 64]
    const float* a_heads = (const float*)d_in[3];   // [4, 128]
    const float* W_out   = (const float*)d_in[4];   // [256, 121]
    const float* a_out   = (const float*)d_in[5];   // [242]
    float* out = (float*)d_out;                     // [8192, 121]

    float *dWh, *dWh2, *dHcat;
    cudaGetSymbolAddress((void**)&dWh,   g_Wh);
    cudaGetSymbolAddress((void**)&dWh2,  g_Wh2);
    cudaGetSymbolAddress((void**)&dHcat, g_hcat);

    static cudaStream_t s_side = []() {
        cudaStream_t s; cudaStreamCreateWithFlags(&s, cudaStreamNonBlocking); return s;
    }();
    static cudaEvent_t ev_fork = []() {
        cudaEvent_t e; cudaEventCreateWithFlags(&e, cudaEventDisableTiming); return e;
    }();
    static cudaEvent_t ev_join = []() {
        cudaEvent_t e; cudaEventCreateWithFlags(&e, cudaEventDisableTiming); return e;
    }();

    // fork: CSR build (DRAM-bound) runs concurrently with GEMM1 (FMA-bound)
    cudaEventRecord(ev_fork, 0);
    cudaStreamWaitEvent(s_side, ev_fork, 0);
    build_csr<<<N_NODES / 8, 256, 0, s_side>>>(adj);
    cudaEventRecord(ev_join, s_side);

    // main stream: layer-1 GEMM with fused f1 epilogue (512 blocks)
    sgemm4<0><<<dim3(4, N_NODES / 64), 256>>>(x, Ws, a_heads, dWh, 256);

    // join: aggregation needs both CSR and scores
    cudaStreamWaitEvent(0, ev_join, 0);
    layer1_agg<<<N_NODES / 4, 256>>>();

    // layer 2: GEMM with fused f2-partials epilogue (256 blocks), then aggregate
    sgemm4<1><<<dim3(2, N_NODES / 64), 256>>>(dHcat, W_out, a_out, dWh2, 128);
    layer2_agg<<<N_NODES / 4, 256>>>(out);
}

// round 8
// speedup vs baseline: 1.0522x; 1.0522x over previous
#include <cuda_runtime.h>
#include <cuda_bf16.h>

#define N_NODES 8192
#define NFEAT   256
#define NHID    64
#define NHEADS  4
#define NCLASS  121
#define MAXDEG  256
#define ALPHA_LRELU 0.2f

// ---------------- scratch (static device globals; no allocation) ----------------
__device__ int   g_deg[N_NODES];
__device__ int   g_nbr[N_NODES * MAXDEG];
__device__ float g_Wh [N_NODES * 256];        // layer-1 Wh, all 4 heads concatenated
__device__ float g_fsrc[N_NODES * NHEADS];    // interleaved [node][head]
__device__ float g_fdst[N_NODES * NHEADS];    // interleaved [node][head]
__device__ float g_hcat[N_NODES * 256];
__device__ float g_Wh2[N_NODES * 128];        // layer-2 Wh, padded to 128 cols
__device__ float g_w2src[256];                // W_out @ a_out[:121]
__device__ float g_w2dst[256];                // W_out @ a_out[121:]
__device__ float g_f2src[N_NODES];
__device__ float g_f2dst[N_NODES];

// ------- CSR build: warp per row, ballot compaction, 4-deep load batching -------
__global__ __launch_bounds__(256) void build_csr(const float* __restrict__ adj) {
    int warp = (blockIdx.x * blockDim.x + threadIdx.x) >> 5;
    int lane = threadIdx.x & 31;
    if (warp >= N_NODES) return;
    const float4* row = reinterpret_cast<const float4*>(adj + (size_t)warp * N_NODES);
    int cnt = 0;
    int* out = g_nbr + warp * MAXDEG;
    for (int base = 0; base < N_NODES / 4; base += 128) {
        float4 v[4];
        #pragma unroll
        for (int r = 0; r < 4; r++) v[r] = row[base + r * 32 + lane];
        #pragma unroll
        for (int r = 0; r < 4; r++) {
            float vv[4] = {v[r].x, v[r].y, v[r].z, v[r].w};
            int col0 = (base + r * 32 + lane) * 4;
            #pragma unroll
            for (int q = 0; q < 4; q++) {
                unsigned m = __ballot_sync(0xffffffffu, vv[q] > 0.0f);
                if (vv[q] > 0.0f) {
                    int pos = cnt + __popc(m & ((1u << lane) - 1u));
                    if (pos < MAXDEG) out[pos] = col0 + q;
                }
                cnt += __popc(m);
            }
        }
    }
    if (lane == 0) g_deg[warp] = cnt < MAXDEG ? cnt : MAXDEG;
}

// ------- tiny: w~ = W_out @ a_out halves (1 block, 256 threads) -----------------
__global__ __launch_bounds__(256) void prep_wtilde(const float* __restrict__ W_out,
                                                   const float* __restrict__ a_out) {
    int k = threadIdx.x;   // 0..255
    const float* wrow = W_out + (size_t)k * NCLASS;
    float s = 0.0f, d = 0.0f;
    for (int c = 0; c < NCLASS; c++) {
        float w = wrow[c];
        s = fmaf(w, a_out[c], s);
        d = fmaf(w, a_out[NCLASS + c], d);
    }
    g_w2src[k] = s;
    g_w2dst[k] = d;
}

// ------- double-buffered fp32 GEMM: BM=64, BN=64, BK=16, 256 thr, 4x4 -----------
// MODE 0: B(k,c) = Ws[(c>>6)*NFEAT*NHID + k*NHID + (c&63)]; epilogue computes
//         f_src/f_dst for this head (BN == NHID) via in-register dot + shuffle.
// MODE 1: B(k,c) = (c<NCLASS) ? W_out[k*NCLASS + c] : 0; pure GEMM.
template <int MODE>
__global__ __launch_bounds__(256) void sgemm5(const float* __restrict__ A,
                                              const float* __restrict__ B,
                                              const float* __restrict__ avec,
                                              float* __restrict__ C, int ldc) {
    __shared__ float sA[2][16][68];
    __shared__ float sB[2][16][68];

    int tid = threadIdx.x;
    int m0 = blockIdx.y * 64;
    int c0 = blockIdx.x * 64;

    int ar  = tid >> 2;            // 0..63
    int ac4 = (tid & 3) * 4;       // 0,4,8,12
    int bk  = tid >> 4;            // 0..15
    int bc4 = (tid & 15) * 4;      // 0..60

    int ty = tid >> 4;             // 0..15
    int tx = tid & 15;             // 0..15

    float acc[4][4];
    #pragma unroll
    for (int i = 0; i < 4; i++)
        #pragma unroll
        for (int j = 0; j < 4; j++) acc[i][j] = 0.0f;

    // preload tile 0
    float4 a_n = *reinterpret_cast<const float4*>(A + (size_t)(m0 + ar) * NFEAT + ac4);
    float4 b_n;
    if (MODE == 0) {
        b_n = *reinterpret_cast<const float4*>(
            B + (size_t)(c0 >> 6) * (NFEAT * NHID) + (size_t)bk * NHID + bc4);
    } else {
        float* bb = reinterpret_cast<float*>(&b_n);
        #pragma unroll
        for (int j = 0; j < 4; j++) {
            int c = c0 + bc4 + j;
            bb[j] = (c < NCLASS) ? B[(size_t)bk * NCLASS + c] : 0.0f;
        }
    }
    sA[0][ac4 + 0][ar] = a_n.x;
    sA[0][ac4 + 1][ar] = a_n.y;
    sA[0][ac4 + 2][ar] = a_n.z;
    sA[0][ac4 + 3][ar] = a_n.w;
    sB[0][bk][bc4 + 0] = b_n.x;
    sB[0][bk][bc4 + 1] = b_n.y;
    sB[0][bk][bc4 + 2] = b_n.z;
    sB[0][bk][bc4 + 3] = b_n.w;
    __syncthreads();

    int buf = 0;
    #pragma unroll 1
    for (int t = 0; t < 16; t++) {
        // prefetch tile t+1 into registers (latency hidden under compute)
        if (t < 15) {
            int k0 = (t + 1) * 16;
            a_n = *reinterpret_cast<const float4*>(A + (size_t)(m0 + ar) * NFEAT + k0 + ac4);
            if (MODE == 0) {
                b_n = *reinterpret_cast<const float4*>(
                    B + (size_t)(c0 >> 6) * (NFEAT * NHID) + (size_t)(k0 + bk) * NHID + bc4);
            } else {
                float* bb = reinterpret_cast<float*>(&b_n);
                #pragma unroll
                for (int j = 0; j < 4; j++) {
                    int c = c0 + bc4 + j;
                    bb[j] = (c < NCLASS) ? B[(size_t)(k0 + bk) * NCLASS + c] : 0.0f;
                }
            }
        }

        #pragma unroll
        for (int kk = 0; kk < 16; kk++) {
            float4 a4 = *reinterpret_cast<const float4*>(&sA[buf][kk][ty * 4]);
            float4 b4 = *reinterpret_cast<const float4*>(&sB[buf][kk][tx * 4]);
            float a[4] = {a4.x, a4.y, a4.z, a4.w};
            float b[4] = {b4.x, b4.y, b4.z, b4.w};
            #pragma unroll
            for (int i = 0; i < 4; i++)
                #pragma unroll
                for (int j = 0; j < 4; j++) acc[i][j] = fmaf(a[i], b[j], acc[i][j]);
        }

        if (t < 15) {
            int nb = buf ^ 1;
            sA[nb][ac4 + 0][ar] = a_n.x;
            sA[nb][ac4 + 1][ar] = a_n.y;
            sA[nb][ac4 + 2][ar] = a_n.z;
            sA[nb][ac4 + 3][ar] = a_n.w;
            sB[nb][bk][bc4 + 0] = b_n.x;
            sB[nb][bk][bc4 + 1] = b_n.y;
            sB[nb][bk][bc4 + 2] = b_n.z;
            sB[nb][bk][bc4 + 3] = b_n.w;
            __syncthreads();
            buf = nb;
        }
    }

    #pragma unroll
    for (int i = 0; i < 4; i++) {
        float4 v = make_float4(acc[i][0], acc[i][1], acc[i][2], acc[i][3]);
        *reinterpret_cast<float4*>(C + (size_t)(m0 + ty * 4 + i) * ldc + c0 + tx * 4) = v;
    }

    // -------- fused f1 epilogue (MODE 0 only) --------
    if (MODE == 0) {
        const float* ah = avec + (c0 >> 6) * (2 * NHID);
        float as[4], ad[4];
        #pragma unroll
        for (int j = 0; j < 4; j++) {
            as[j] = ah[tx * 4 + j];
            ad[j] = ah[NHID + tx * 4 + j];
        }
        #pragma unroll
        for (int i = 0; i < 4; i++) {
            float s = fmaf(acc[i][0], as[0], acc[i][1] * as[1]) +
                      fmaf(acc[i][2], as[2], acc[i][3] * as[3]);
            float d = fmaf(acc[i][0], ad[0], acc[i][1] * ad[1]) +
                      fmaf(acc[i][2], ad[2], acc[i][3] * ad[3]);
            #pragma unroll
            for (int o = 1; o < 16; o <<= 1) {
                s += __shfl_xor_sync(0xffffffffu, s, o);
                d += __shfl_xor_sync(0xffffffffu, d, o);
            }
            if (tx == 0) {
                int row = m0 + ty * 4 + i;
                int h = c0 >> 6;
                g_fsrc[row * 4 + h] = s;
                g_fdst[row * 4 + h] = d;
            }
        }
    }
}

// ---- layer-1 sparse attention + aggregate + ELU + fused f2 scores (4 nodes/blk)
__global__ __launch_bounds__(256) void layer1_agg() {
    __shared__ int   s_nbr[4][MAXDEG];
    __shared__ float s_w[4][NHEADS][MAXDEG];
    __shared__ float s_red[4][NHEADS][2];
    __shared__ float s_wt[512];           // w~src[256] then w~dst[256]
    __shared__ float s_p[4][2][2];        // [group][src/dst][wig]

    int tid  = threadIdx.x;
    int g    = tid >> 6;          // group 0..3
    int lt   = tid & 63;          // lane in group
    int wig  = lt >> 5;           // warp in group 0..1
    int lane = tid & 31;

    int i   = blockIdx.x * 4 + g;
    int deg = g_deg[i];

    s_wt[tid]       = (tid < 256) ? g_w2src[tid] : 0.0f;
    s_wt[256 + tid % 256] = g_w2dst[tid % 256];   // overwritten consistently
    // simpler deterministic fill:
    if (tid < 256) { s_wt[tid] = g_w2src[tid]; s_wt[256 + tid] = g_w2dst[tid]; }

    for (int t = lt; t < deg; t += 64) s_nbr[g][t] = g_nbr[i * MAXDEG + t];
    __syncthreads();

    float4 fs = *reinterpret_cast<const float4*>(g_fsrc + (size_t)i * 4);
    float fsrcA[4] = {fs.x, fs.y, fs.z, fs.w};

    float lmax[4] = {-1e30f, -1e30f, -1e30f, -1e30f};
    for (int j = lt; j < deg; j += 64) {
        float4 fd = *reinterpret_cast<const float4*>(g_fdst + (size_t)s_nbr[g][j] * 4);
        float fdA[4] = {fd.x, fd.y, fd.z, fd.w};
        #pragma unroll
        for (int h = 0; h < 4; h++) {
            float e = fsrcA[h] + fdA[h];
            e = e >= 0.0f ? e : ALPHA_LRELU * e;
            s_w[g][h][j] = e;
            lmax[h] = fmaxf(lmax[h], e);
        }
    }
    #pragma unroll
    for (int h = 0; h < 4; h++) {
        #pragma unroll
        for (int o = 16; o; o >>= 1) lmax[h] = fmaxf(lmax[h], __shfl_xor_sync(0xffffffffu, lmax[h], o));
        if (lane == 0) s_red[g][h][wig] = lmax[h];
    }
    __syncthreads();
    float m[4];
    #pragma unroll
    for (int h = 0; h < 4; h++) m[h] = fmaxf(s_red[g][h][0], s_red[g][h][1]);

    float lsum[4] = {0.0f, 0.0f, 0.0f, 0.0f};
    for (int j = lt; j < deg; j += 64) {
        #pragma unroll
        for (int h = 0; h < 4; h++) {
            float w = __expf(s_w[g][h][j] - m[h]);
            s_w[g][h][j] = w;
            lsum[h] += w;
        }
    }
    __syncthreads();
    #pragma unroll
    for (int h = 0; h < 4; h++) {
        #pragma unroll
        for (int o = 16; o; o >>= 1) lsum[h] += __shfl_xor_sync(0xffffffffu, lsum[h], o);
        if (lane == 0) s_red[g][h][wig] = lsum[h];
    }
    __syncthreads();

    // gather: thread lt covers hcat cols 4*lt..4*lt+3 (head h2 = lt>>4), 8-deep MLP
    int h2 = lt >> 4;
    float inv = 1.0f / (s_red[g][h2][0] + s_red[g][h2][1]);
    const float4* wh4 = reinterpret_cast<const float4*>(g_Wh);
    const float* wrow = s_w[g][h2];
    const int*   nrow = s_nbr[g];

    float4 acc0 = make_float4(0.f, 0.f, 0.f, 0.f);
    float4 acc1 = make_float4(0.f, 0.f, 0.f, 0.f);
    int j = 0;
    for (; j + 7 < deg; j += 8) {
        float w0 = wrow[j],     w1 = wrow[j + 1], w2 = wrow[j + 2], w3 = wrow[j + 3];
        float w4 = wrow[j + 4], w5 = wrow[j + 5], w6 = wrow[j + 6], w7 = wrow[j + 7];
        float4 v0 = wh4[(size_t)nrow[j]     * 64 + lt];
        float4 v1 = wh4[(size_t)nrow[j + 1] * 64 + lt];
        float4 v2 = wh4[(size_t)nrow[j + 2] * 64 + lt];
        float4 v3 = wh4[(size_t)nrow[j + 3] * 64 + lt];
        float4 v4 = wh4[(size_t)nrow[j + 4] * 64 + lt];
        float4 v5 = wh4[(size_t)nrow[j + 5] * 64 + lt];
        float4 v6 = wh4[(size_t)nrow[j + 6] * 64 + lt];
        float4 v7 = wh4[(size_t)nrow[j + 7] * 64 + lt];
        acc0.x = fmaf(w0, v0.x, acc0.x); acc0.y = fmaf(w0, v0.y, acc0.y);
        acc0.z = fmaf(w0, v0.z, acc0.z); acc0.w = fmaf(w0, v0.w, acc0.w);
        acc1.x = fmaf(w1, v1.x, acc1.x); acc1.y = fmaf(w1, v1.y, acc1.y);
        acc1.z = fmaf(w1, v1.z, acc1.z); acc1.w = fmaf(w1, v1.w, acc1.w);
        acc0.x = fmaf(w2, v2.x, acc0.x); acc0.y = fmaf(w2, v2.y, acc0.y);
        acc0.z = fmaf(w2, v2.z, acc0.z); acc0.w = fmaf(w2, v2.w, acc0.w);
        acc1.x = fmaf(w3, v3.x, acc1.x); acc1.y = fmaf(w3, v3.y, acc1.y);
        acc1.z = fmaf(w3, v3.z, acc1.z); acc1.w = fmaf(w3, v3.w, acc1.w);
        acc0.x = fmaf(w4, v4.x, acc0.x); acc0.y = fmaf(w4, v4.y, acc0.y);
        acc0.z = fmaf(w4, v4.z, acc0.z); acc0.w = fmaf(w4, v4.w, acc0.w);
        acc1.x = fmaf(w5, v5.x, acc1.x); acc1.y = fmaf(w5, v5.y, acc1.y);
        acc1.z = fmaf(w5, v5.z, acc1.z); acc1.w = fmaf(w5, v5.w, acc1.w);
        acc0.x = fmaf(w6, v6.x, acc0.x); acc0.y = fmaf(w6, v6.y, acc0.y);
        acc0.z = fmaf(w6, v6.z, acc0.z); acc0.w = fmaf(w6, v6.w, acc0.w);
        acc1.x = fmaf(w7, v7.x, acc1.x); acc1.y = fmaf(w7, v7.y, acc1.y);
        acc1.z = fmaf(w7, v7.z, acc1.z); acc1.w = fmaf(w7, v7.w, acc1.w);
    }
    for (; j < deg; j++) {
        float w0 = wrow[j];
        float4 v0 = wh4[(size_t)nrow[j] * 64 + lt];
        acc0.x = fmaf(w0, v0.x, acc0.x); acc0.y = fmaf(w0, v0.y, acc0.y);
        acc0.z = fmaf(w0, v0.z, acc0.z); acc0.w = fmaf(w0, v0.w, acc0.w);
    }
    float4 r;
    r.x = (acc0.x + acc1.x) * inv;
    r.y = (acc0.y + acc1.y) * inv;
    r.z = (acc0.z + acc1.z) * inv;
    r.w = (acc0.w + acc1.w) * inv;
    r.x = r.x > 0.0f ? r.x : expm1f(r.x);
    r.y = r.y > 0.0f ? r.y : expm1f(r.y);
    r.z = r.z > 0.0f ? r.z : expm1f(r.z);
    r.w = r.w > 0.0f ? r.w : expm1f(r.w);
    reinterpret_cast<float4*>(g_hcat)[(size_t)i * 64 + lt] = r;

    // -------- fused layer-2 score: f2 = hcat_row . w~ --------
    int c4 = lt * 4;
    float ps = fmaf(r.x, s_wt[c4], r.y * s_wt[c4 + 1]) +
               fmaf(r.z, s_wt[c4 + 2], r.w * s_wt[c4 + 3]);
    float pd = fmaf(r.x, s_wt[256 + c4], r.y * s_wt[256 + c4 + 1]) +
               fmaf(r.z, s_wt[256 + c4 + 2], r.w * s_wt[256 + c4 + 3]);
    #pragma unroll
    for (int o = 16; o; o >>= 1) {
        ps += __shfl_xor_sync(0xffffffffu, ps, o);
        pd += __shfl_xor_sync(0xffffffffu, pd, o);
    }
    if (lane == 0) { s_p[g][0][wig] = ps; s_p[g][1][wig] = pd; }
    __syncthreads();
    if (lt == 0) {
        g_f2src[i] = s_p[g][0][0] + s_p[g][0][1];
        g_f2dst[i] = s_p[g][1][0] + s_p[g][1][1];
    }
}

// ---------------- layer-2 sparse attention + aggregate (4 nodes/block) ----------
__global__ __launch_bounds__(256) void layer2_agg(float* __restrict__ out) {
    __shared__ int   s_nbr[4][MAXDEG];
    __shared__ float s_w[4][MAXDEG];
    __shared__ float s_red[4][2];

    int tid  = threadIdx.x;
    int g    = tid >> 6;
    int lt   = tid & 63;
    int wig  = lt >> 5;
    int lane = tid & 31;

    int i   = blockIdx.x * 4 + g;
    int deg = g_deg[i];

    for (int t = lt; t < deg; t += 64) s_nbr[g][t] = g_nbr[i * MAXDEG + t];
    __syncthreads();

    float fsrc = g_f2src[i];
    float lmax = -1e30f;
    for (int j = lt; j < deg; j += 64) {
        float e = fsrc + g_f2dst[s_nbr[g][j]];
        e = e >= 0.0f ? e : ALPHA_LRELU * e;
        s_w[g][j] = e;
        lmax = fmaxf(lmax, e);
    }
    #pragma unroll
    for (int o = 16; o; o >>= 1) lmax = fmaxf(lmax, __shfl_xor_sync(0xffffffffu, lmax, o));
    if (lane == 0) s_red[g][wig] = lmax;
    __syncthreads();
    float m = fmaxf(s_red[g][0], s_red[g][1]);

    float lsum = 0.0f;
    for (int j = lt; j < deg; j += 64) {
        float w = __expf(s_w[g][j] - m);
        s_w[g][j] = w;
        lsum += w;
    }
    __syncthreads();
    #pragma unroll
    for (int o = 16; o; o >>= 1) lsum += __shfl_xor_sync(0xffffffffu, lsum, o);
    if (lane == 0) s_red[g][wig] = lsum;
    __syncthreads();
    float inv = 1.0f / (s_red[g][0] + s_red[g][1]);

    const float2* wh2 = reinterpret_cast<const float2*>(g_Wh2);
    const float*  wrow = s_w[g];
    const int*    nrow = s_nbr[g];
    float2 acc0 = make_float2(0.f, 0.f);
    float2 acc1 = make_float2(0.f, 0.f);
    int j = 0;
    for (; j + 7 < deg; j += 8) {
        float w0 = wrow[j],     w1 = wrow[j + 1], w2 = wrow[j + 2], w3 = wrow[j + 3];
        float w4 = wrow[j + 4], w5 = wrow[j + 5], w6 = wrow[j + 6], w7 = wrow[j + 7];
        float2 v0 = wh2[(size_t)nrow[j]     * 64 + lt];
        float2 v1 = wh2[(size_t)nrow[j + 1] * 64 + lt];
        float2 v2 = wh2[(size_t)nrow[j + 2] * 64 + lt];
        float2 v3 = wh2[(size_t)nrow[j + 3] * 64 + lt];
        float2 v4 = wh2[(size_t)nrow[j + 4] * 64 + lt];
        float2 v5 = wh2[(size_t)nrow[j + 5] * 64 + lt];
        float2 v6 = wh2[(size_t)nrow[j + 6] * 64 + lt];
        float2 v7 = wh2[(size_t)nrow[j + 7] * 64 + lt];
        acc0.x = fmaf(w0, v0.x, acc0.x); acc0.y = fmaf(w0, v0.y, acc0.y);
        acc1.x = fmaf(w1, v1.x, acc1.x); acc1.y = fmaf(w1, v1.y, acc1.y);
        acc0.x = fmaf(w2, v2.x, acc0.x); acc0.y = fmaf(w2, v2.y, acc0.y);
        acc1.x = fmaf(w3, v3.x, acc1.x); acc1.y = fmaf(w3, v3.y, acc1.y);
        acc0.x = fmaf(w4, v4.x, acc0.x); acc0.y = fmaf(w4, v4.y, acc0.y);
        acc1.x = fmaf(w5, v5.x, acc1.x); acc1.y = fmaf(w5, v5.y, acc1.y);
        acc0.x = fmaf(w6, v6.x, acc0.x); acc0.y = fmaf(w6, v6.y, acc0.y);
        acc1.x = fmaf(w7, v7.x, acc1.x); acc1.y = fmaf(w7, v7.y, acc1.y);
    }
    for (; j < deg; j++) {
        float w0 = wrow[j];
        float2 v0 = wh2[(size_t)nrow[j] * 64 + lt];
        acc0.x = fmaf(w0, v0.x, acc0.x); acc0.y = fmaf(w0, v0.y, acc0.y);
    }
    int c = lt * 2;
    if (c < NCLASS)     out[(size_t)i * NCLASS + c]     = (acc0.x + acc1.x) * inv;
    if (c + 1 < NCLASS) out[(size_t)i * NCLASS + c + 1] = (acc0.y + acc1.y) * inv;
}

// ---------------- host launch ---------------------------------------------------
extern "C" void kernel_launch(void* const* d_in, const int* in_sizes, int n_in,
                              void* d_out, int out_size) {
    const float* x       = (const float*)d_in[0];   // [8192, 256]
    const float* adj     = (const float*)d_in[1];   // [8192, 8192]
    const float* Ws      = (const float*)d_in[2];   // [4, 256, 64]
    const float* a_heads = (const float*)d_in[3];   // [4, 128]
    const float* W_out   = (const float*)d_in[4];   // [256, 121]
    const float* a_out   = (const float*)d_in[5];   // [242]
    float* out = (float*)d_out;                     // [8192, 121]

    float *dWh, *dWh2, *dHcat;
    cudaGetSymbolAddress((void**)&dWh,   g_Wh);
    cudaGetSymbolAddress((void**)&dWh2,  g_Wh2);
    cudaGetSymbolAddress((void**)&dHcat, g_hcat);

    static cudaStream_t s_side = []() {
        cudaStream_t s; cudaStreamCreateWithFlags(&s, cudaStreamNonBlocking); return s;
    }();
    static cudaEvent_t ev_fork = []() {
        cudaEvent_t e; cudaEventCreateWithFlags(&e, cudaEventDisableTiming); return e;
    }();
    static cudaEvent_t ev_join = []() {
        cudaEvent_t e; cudaEventCreateWithFlags(&e, cudaEventDisableTiming); return e;
    }();

    // fork: CSR build (DRAM-bound) runs concurrently with GEMM1 (FMA-bound)
    cudaEventRecord(ev_fork, 0);
    cudaStreamWaitEvent(s_side, ev_fork, 0);
    build_csr<<<N_NODES / 8, 256, 0, s_side>>>(adj);
    cudaEventRecord(ev_join, s_side);

    // main stream: w~ prep (tiny), then layer-1 GEMM with fused f1 epilogue
    prep_wtilde<<<1, 256>>>(W_out, a_out);
    sgemm5<0><<<dim3(4, N_NODES / 64), 256>>>(x, Ws, a_heads, dWh, 256);

    // join: aggregation needs CSR + scores + w~
    cudaStreamWaitEvent(0, ev_join, 0);
    layer1_agg<<<N_NODES / 4, 256>>>();

    // layer 2: pure double-buffered GEMM, then aggregate
    sgemm5<1><<<dim3(2, N_NODES / 64), 256>>>(dHcat, W_out, nullptr, dWh2, 128);
    layer2_agg<<<N_NODES / 4, 256>>>(out);
}

// round 9
// speedup vs baseline: 1.1610x; 1.1034x over previous
#include <cuda_runtime.h>
#include <cuda_bf16.h>
#include <cuda_fp16.h>

#define N_NODES 8192
#define NFEAT   256
#define NHID    64
#define NHEADS  4
#define NCLASS  121
#define MAXDEG  256
#define ALPHA_LRELU 0.2f

// ---------------- scratch (static device globals; no allocation) ----------------
__device__ int   g_deg[N_NODES];
__device__ int   g_nbr[N_NODES * MAXDEG];
__device__ uint2 g_Wh_h [N_NODES * 64];       // layer-1 Wh in fp16 (4 halves per uint2)
__device__ float g_fsrc[N_NODES * NHEADS];    // interleaved [node][head]
__device__ float g_fdst[N_NODES * NHEADS];    // interleaved [node][head]
__device__ float g_hcat[N_NODES * 256];
__device__ unsigned g_Wh2h[N_NODES * 64];     // layer-2 Wh in fp16 (2 halves per uint)
__device__ float g_f2srcp[2][N_NODES];        // layer-2 score partials per col-block
__device__ float g_f2dstp[2][N_NODES];

// ------- CSR build: warp per row, ballot compaction, 4-deep load batching -------
__global__ __launch_bounds__(256) void build_csr(const float* __restrict__ adj) {
    int warp = (blockIdx.x * blockDim.x + threadIdx.x) >> 5;
    int lane = threadIdx.x & 31;
    if (warp >= N_NODES) return;
    const float4* row = reinterpret_cast<const float4*>(adj + (size_t)warp * N_NODES);
    int cnt = 0;
    int* out = g_nbr + warp * MAXDEG;
    for (int base = 0; base < N_NODES / 4; base += 128) {
        float4 v[4];
        #pragma unroll
        for (int r = 0; r < 4; r++) v[r] = row[base + r * 32 + lane];
        #pragma unroll
        for (int r = 0; r < 4; r++) {
            float vv[4] = {v[r].x, v[r].y, v[r].z, v[r].w};
            int col0 = (base + r * 32 + lane) * 4;
            #pragma unroll
            for (int q = 0; q < 4; q++) {
                unsigned m = __ballot_sync(0xffffffffu, vv[q] > 0.0f);
                if (vv[q] > 0.0f) {
                    int pos = cnt + __popc(m & ((1u << lane) - 1u));
                    if (pos < MAXDEG) out[pos] = col0 + q;
                }
                cnt += __popc(m);
            }
        }
    }
    if (lane == 0) g_deg[warp] = cnt < MAXDEG ? cnt : MAXDEG;
}

// ------- double-buffered fp32 GEMM: BM=64, BN=64, BK=16, 256 thr, 4x4 -----------
// MODE 0: B(k,c) = Ws[...]; stores fp16 Wh; epilogue computes f1 src/dst scores.
// MODE 1: B(k,c) = W_out (padded); stores fp16 Wh2; epilogue computes f2 partials.
template <int MODE>
__global__ __launch_bounds__(256) void sgemm6(const float* __restrict__ A,
                                              const float* __restrict__ B,
                                              const float* __restrict__ avec) {
    __shared__ float sA[2][16][68];
    __shared__ float sB[2][16][68];

    int tid = threadIdx.x;
    int m0 = blockIdx.y * 64;
    int c0 = blockIdx.x * 64;

    int ar  = tid >> 2;            // 0..63
    int ac4 = (tid & 3) * 4;       // 0,4,8,12
    int bk  = tid >> 4;            // 0..15
    int bc4 = (tid & 15) * 4;      // 0..60

    int ty = tid >> 4;             // 0..15
    int tx = tid & 15;             // 0..15

    float acc[4][4];
    #pragma unroll
    for (int i = 0; i < 4; i++)
        #pragma unroll
        for (int j = 0; j < 4; j++) acc[i][j] = 0.0f;

    // preload tile 0
    float4 a_n = *reinterpret_cast<const float4*>(A + (size_t)(m0 + ar) * NFEAT + ac4);
    float4 b_n;
    if (MODE == 0) {
        b_n = *reinterpret_cast<const float4*>(
            B + (size_t)(c0 >> 6) * (NFEAT * NHID) + (size_t)bk * NHID + bc4);
    } else {
        float* bb = reinterpret_cast<float*>(&b_n);
        #pragma unroll
        for (int j = 0; j < 4; j++) {
            int c = c0 + bc4 + j;
            bb[j] = (c < NCLASS) ? B[(size_t)bk * NCLASS + c] : 0.0f;
        }
    }
    sA[0][ac4 + 0][ar] = a_n.x;
    sA[0][ac4 + 1][ar] = a_n.y;
    sA[0][ac4 + 2][ar] = a_n.z;
    sA[0][ac4 + 3][ar] = a_n.w;
    sB[0][bk][bc4 + 0] = b_n.x;
    sB[0][bk][bc4 + 1] = b_n.y;
    sB[0][bk][bc4 + 2] = b_n.z;
    sB[0][bk][bc4 + 3] = b_n.w;
    __syncthreads();

    int buf = 0;
    #pragma unroll 1
    for (int t = 0; t < 16; t++) {
        if (t < 15) {
            int k0 = (t + 1) * 16;
            a_n = *reinterpret_cast<const float4*>(A + (size_t)(m0 + ar) * NFEAT + k0 + ac4);
            if (MODE == 0) {
                b_n = *reinterpret_cast<const float4*>(
                    B + (size_t)(c0 >> 6) * (NFEAT * NHID) + (size_t)(k0 + bk) * NHID + bc4);
            } else {
                float* bb = reinterpret_cast<float*>(&b_n);
                #pragma unroll
                for (int j = 0; j < 4; j++) {
                    int c = c0 + bc4 + j;
                    bb[j] = (c < NCLASS) ? B[(size_t)(k0 + bk) * NCLASS + c] : 0.0f;
                }
            }
        }

        #pragma unroll
        for (int kk = 0; kk < 16; kk++) {
            float4 a4 = *reinterpret_cast<const float4*>(&sA[buf][kk][ty * 4]);
            float4 b4 = *reinterpret_cast<const float4*>(&sB[buf][kk][tx * 4]);
            float a[4] = {a4.x, a4.y, a4.z, a4.w};
            float b[4] = {b4.x, b4.y, b4.z, b4.w};
            #pragma unroll
            for (int i = 0; i < 4; i++)
                #pragma unroll
                for (int j = 0; j < 4; j++) acc[i][j] = fmaf(a[i], b[j], acc[i][j]);
        }

        if (t < 15) {
            int nb = buf ^ 1;
            sA[nb][ac4 + 0][ar] = a_n.x;
            sA[nb][ac4 + 1][ar] = a_n.y;
            sA[nb][ac4 + 2][ar] = a_n.z;
            sA[nb][ac4 + 3][ar] = a_n.w;
            sB[nb][bk][bc4 + 0] = b_n.x;
            sB[nb][bk][bc4 + 1] = b_n.y;
            sB[nb][bk][bc4 + 2] = b_n.z;
            sB[nb][bk][bc4 + 3] = b_n.w;
            __syncthreads();
            buf = nb;
        }
    }

    // -------- fp16 stores --------
    #pragma unroll
    for (int i = 0; i < 4; i++) {
        int row = m0 + ty * 4 + i;
        __half2 h01 = __floats2half2_rn(acc[i][0], acc[i][1]);
        __half2 h23 = __floats2half2_rn(acc[i][2], acc[i][3]);
        uint2 u;
        u.x = *reinterpret_cast<unsigned*>(&h01);
        u.y = *reinterpret_cast<unsigned*>(&h23);
        if (MODE == 0) {
            // Wh: 256 cols -> 64 uint2 per row
            g_Wh_h[(size_t)row * 64 + (c0 >> 2) + tx] = u;
        } else {
            // Wh2: 128 cols -> 64 unsigned per row; write 2 at once (8B aligned)
            *reinterpret_cast<uint2*>(&g_Wh2h[(size_t)row * 64 + (c0 >> 1) + tx * 2]) = u;
        }
    }

    // -------- fused attention-score epilogue (fp32 acc) --------
    float as[4], ad[4];
    if (MODE == 0) {
        const float* ah = avec + (c0 >> 6) * (2 * NHID);
        #pragma unroll
        for (int j = 0; j < 4; j++) {
            as[j] = ah[tx * 4 + j];
            ad[j] = ah[NHID + tx * 4 + j];
        }
    } else {
        #pragma unroll
        for (int j = 0; j < 4; j++) {
            int c = c0 + tx * 4 + j;
            as[j] = (c < NCLASS) ? avec[c] : 0.0f;
            ad[j] = (c < NCLASS) ? avec[NCLASS + c] : 0.0f;
        }
    }
    #pragma unroll
    for (int i = 0; i < 4; i++) {
        float s = fmaf(acc[i][0], as[0], acc[i][1] * as[1]) +
                  fmaf(acc[i][2], as[2], acc[i][3] * as[3]);
        float d = fmaf(acc[i][0], ad[0], acc[i][1] * ad[1]) +
                  fmaf(acc[i][2], ad[2], acc[i][3] * ad[3]);
        #pragma unroll
        for (int o = 1; o < 16; o <<= 1) {
            s += __shfl_xor_sync(0xffffffffu, s, o);
            d += __shfl_xor_sync(0xffffffffu, d, o);
        }
        if (tx == 0) {
            int row = m0 + ty * 4 + i;
            if (MODE == 0) {
                int h = c0 >> 6;
                g_fsrc[row * 4 + h] = s;
                g_fdst[row * 4 + h] = d;
            } else {
                g_f2srcp[blockIdx.x][row] = s;
                g_f2dstp[blockIdx.x][row] = d;
            }
        }
    }
}

// ---- layer-1 sparse attention + aggregate + ELU (4 nodes/block, fp16 gather) ---
__global__ __launch_bounds__(256) void layer1_agg() {
    __shared__ int   s_nbr[4][MAXDEG];
    __shared__ float s_w[4][NHEADS][MAXDEG];
    __shared__ float s_red[4][NHEADS][2];

    int tid  = threadIdx.x;
    int g    = tid >> 6;          // group 0..3
    int lt   = tid & 63;          // lane in group
    int wig  = lt >> 5;           // warp in group 0..1
    int lane = tid & 31;

    int i   = blockIdx.x * 4 + g;
    int deg = g_deg[i];

    for (int t = lt; t < deg; t += 64) s_nbr[g][t] = g_nbr[i * MAXDEG + t];
    __syncthreads();

    float4 fs = *reinterpret_cast<const float4*>(g_fsrc + (size_t)i * 4);
    float fsrcA[4] = {fs.x, fs.y, fs.z, fs.w};

    float lmax[4] = {-1e30f, -1e30f, -1e30f, -1e30f};
    for (int j = lt; j < deg; j += 64) {
        float4 fd = *reinterpret_cast<const float4*>(g_fdst + (size_t)s_nbr[g][j] * 4);
        float fdA[4] = {fd.x, fd.y, fd.z, fd.w};
        #pragma unroll
        for (int h = 0; h < 4; h++) {
            float e = fsrcA[h] + fdA[h];
            e = e >= 0.0f ? e : ALPHA_LRELU * e;
            s_w[g][h][j] = e;
            lmax[h] = fmaxf(lmax[h], e);
        }
    }
    #pragma unroll
    for (int h = 0; h < 4; h++) {
        #pragma unroll
        for (int o = 16; o; o >>= 1) lmax[h] = fmaxf(lmax[h], __shfl_xor_sync(0xffffffffu, lmax[h], o));
        if (lane == 0) s_red[g][h][wig] = lmax[h];
    }
    __syncthreads();
    float m[4];
    #pragma unroll
    for (int h = 0; h < 4; h++) m[h] = fmaxf(s_red[g][h][0], s_red[g][h][1]);

    float lsum[4] = {0.0f, 0.0f, 0.0f, 0.0f};
    for (int j = lt; j < deg; j += 64) {
        #pragma unroll
        for (int h = 0; h < 4; h++) {
            float w = __expf(s_w[g][h][j] - m[h]);
            s_w[g][h][j] = w;
            lsum[h] += w;
        }
    }
    __syncthreads();
    #pragma unroll
    for (int h = 0; h < 4; h++) {
        #pragma unroll
        for (int o = 16; o; o >>= 1) lsum[h] += __shfl_xor_sync(0xffffffffu, lsum[h], o);
        if (lane == 0) s_red[g][h][wig] = lsum[h];
    }
    __syncthreads();

    // gather: thread lt covers cols 4*lt..4*lt+3 (head h2 = lt>>4), fp16, 8-deep MLP
    int h2 = lt >> 4;
    float inv = 1.0f / (s_red[g][h2][0] + s_red[g][h2][1]);
    const float* wrow = s_w[g][h2];
    const int*   nrow = s_nbr[g];

    float4 acc0 = make_float4(0.f, 0.f, 0.f, 0.f);
    float4 acc1 = make_float4(0.f, 0.f, 0.f, 0.f);

    #define L1_STEP(U, W, ACC) {                                               \
        __half2 p0 = *reinterpret_cast<__half2*>(&U.x);                        \
        __half2 p1 = *reinterpret_cast<__half2*>(&U.y);                        \
        float2 f0 = __half22float2(p0);                                        \
        float2 f1 = __half22float2(p1);                                        \
        ACC.x = fmaf(W, f0.x, ACC.x); ACC.y = fmaf(W, f0.y, ACC.y);            \
        ACC.z = fmaf(W, f1.x, ACC.z); ACC.w = fmaf(W, f1.y, ACC.w); }

    int j = 0;
    for (; j + 7 < deg; j += 8) {
        float w0 = wrow[j],     w1 = wrow[j + 1], w2 = wrow[j + 2], w3 = wrow[j + 3];
        float w4 = wrow[j + 4], w5 = wrow[j + 5], w6 = wrow[j + 6], w7 = wrow[j + 7];
        uint2 u0 = g_Wh_h[(size_t)nrow[j]     * 64 + lt];
        uint2 u1 = g_Wh_h[(size_t)nrow[j + 1] * 64 + lt];
        uint2 u2 = g_Wh_h[(size_t)nrow[j + 2] * 64 + lt];
        uint2 u3 = g_Wh_h[(size_t)nrow[j + 3] * 64 + lt];
        uint2 u4 = g_Wh_h[(size_t)nrow[j + 4] * 64 + lt];
        uint2 u5 = g_Wh_h[(size_t)nrow[j + 5] * 64 + lt];
        uint2 u6 = g_Wh_h[(size_t)nrow[j + 6] * 64 + lt];
        uint2 u7 = g_Wh_h[(size_t)nrow[j + 7] * 64 + lt];
        L1_STEP(u0, w0, acc0); L1_STEP(u1, w1, acc1);
        L1_STEP(u2, w2, acc0); L1_STEP(u3, w3, acc1);
        L1_STEP(u4, w4, acc0); L1_STEP(u5, w5, acc1);
        L1_STEP(u6, w6, acc0); L1_STEP(u7, w7, acc1);
    }
    for (; j < deg; j++) {
        float w0 = wrow[j];
        uint2 u0 = g_Wh_h[(size_t)nrow[j] * 64 + lt];
        L1_STEP(u0, w0, acc0);
    }
    #undef L1_STEP

    float4 r;
    r.x = (acc0.x + acc1.x) * inv;
    r.y = (acc0.y + acc1.y) * inv;
    r.z = (acc0.z + acc1.z) * inv;
    r.w = (acc0.w + acc1.w) * inv;
    r.x = r.x > 0.0f ? r.x : expm1f(r.x);
    r.y = r.y > 0.0f ? r.y : expm1f(r.y);
    r.z = r.z > 0.0f ? r.z : expm1f(r.z);
    r.w = r.w > 0.0f ? r.w : expm1f(r.w);
    reinterpret_cast<float4*>(g_hcat)[(size_t)i * 64 + lt] = r;
}

// ---- layer-2 sparse attention + aggregate (4 nodes/block, fp16 gather) ---------
__global__ __launch_bounds__(256) void layer2_agg(float* __restrict__ out) {
    __shared__ int   s_nbr[4][MAXDEG];
    __shared__ float s_w[4][MAXDEG];
    __shared__ float s_red[4][2];

    int tid  = threadIdx.x;
    int g    = tid >> 6;
    int lt   = tid & 63;
    int wig  = lt >> 5;
    int lane = tid & 31;

    int i   = blockIdx.x * 4 + g;
    int deg = g_deg[i];

    for (int t = lt; t < deg; t += 64) s_nbr[g][t] = g_nbr[i * MAXDEG + t];
    __syncthreads();

    float fsrc = g_f2srcp[0][i] + g_f2srcp[1][i];
    float lmax = -1e30f;
    for (int j = lt; j < deg; j += 64) {
        int nb = s_nbr[g][j];
        float e = fsrc + g_f2dstp[0][nb] + g_f2dstp[1][nb];
        e = e >= 0.0f ? e : ALPHA_LRELU * e;
        s_w[g][j] = e;
        lmax = fmaxf(lmax, e);
    }
    #pragma unroll
    for (int o = 16; o; o >>= 1) lmax = fmaxf(lmax, __shfl_xor_sync(0xffffffffu, lmax, o));
    if (lane == 0) s_red[g][wig] = lmax;
    __syncthreads();
    float m = fmaxf(s_red[g][0], s_red[g][1]);

    float lsum = 0.0f;
    for (int j = lt; j < deg; j += 64) {
        float w = __expf(s_w[g][j] - m);
        s_w[g][j] = w;
        lsum += w;
    }
    __syncthreads();
    #pragma unroll
    for (int o = 16; o; o >>= 1) lsum += __shfl_xor_sync(0xffffffffu, lsum, o);
    if (lane == 0) s_red[g][wig] = lsum;
    __syncthreads();
    float inv = 1.0f / (s_red[g][0] + s_red[g][1]);

    // gather: thread lt covers cols 2*lt, 2*lt+1 (one half2 each), 8-deep MLP
    const float*  wrow = s_w[g];
    const int*    nrow = s_nbr[g];
    float2 acc0 = make_float2(0.f, 0.f);
    float2 acc1 = make_float2(0.f, 0.f);

    #define L2_STEP(U, W, ACC) {                                               \
        float2 f = __half22float2(*reinterpret_cast<__half2*>(&U));            \
        ACC.x = fmaf(W, f.x, ACC.x); ACC.y = fmaf(W, f.y, ACC.y); }

    int j = 0;
    for (; j + 7 < deg; j += 8) {
        float w0 = wrow[j],     w1 = wrow[j + 1], w2 = wrow[j + 2], w3 = wrow[j + 3];
        float w4 = wrow[j + 4], w5 = wrow[j + 5], w6 = wrow[j + 6], w7 = wrow[j + 7];
        unsigned u0 = g_Wh2h[(size_t)nrow[j]     * 64 + lt];
        unsigned u1 = g_Wh2h[(size_t)nrow[j + 1] * 64 + lt];
        unsigned u2 = g_Wh2h[(size_t)nrow[j + 2] * 64 + lt];
        unsigned u3 = g_Wh2h[(size_t)nrow[j + 3] * 64 + lt];
        unsigned u4 = g_Wh2h[(size_t)nrow[j + 4] * 64 + lt];
        unsigned u5 = g_Wh2h[(size_t)nrow[j + 5] * 64 + lt];
        unsigned u6 = g_Wh2h[(size_t)nrow[j + 6] * 64 + lt];
        unsigned u7 = g_Wh2h[(size_t)nrow[j + 7] * 64 + lt];
        L2_STEP(u0, w0, acc0); L2_STEP(u1, w1, acc1);
        L2_STEP(u2, w2, acc0); L2_STEP(u3, w3, acc1);
        L2_STEP(u4, w4, acc0); L2_STEP(u5, w5, acc1);
        L2_STEP(u6, w6, acc0); L2_STEP(u7, w7, acc1);
    }
    for (; j < deg; j++) {
        float w0 = wrow[j];
        unsigned u0 = g_Wh2h[(size_t)nrow[j] * 64 + lt];
        L2_STEP(u0, w0, acc0);
    }
    #undef L2_STEP

    int c = lt * 2;
    if (c < NCLASS)     out[(size_t)i * NCLASS + c]     = (acc0.x + acc1.x) * inv;
    if (c + 1 < NCLASS) out[(size_t)i * NCLASS + c + 1] = (acc0.y + acc1.y) * inv;
}

// ---------------- host launch ---------------------------------------------------
extern "C" void kernel_launch(void* const* d_in, const int* in_sizes, int n_in,
                              void* d_out, int out_size) {
    const float* x       = (const float*)d_in[0];   // [8192, 256]
    const float* adj     = (const float*)d_in[1];   // [8192, 8192]
    const float* Ws      = (const float*)d_in[2];   // [4, 256, 64]
    const float* a_heads = (const float*)d_in[3];   // [4, 128]
    const float* W_out   = (const float*)d_in[4];   // [256, 121]
    const float* a_out   = (const float*)d_in[5];   // [242]
    float* out = (float*)d_out;                     // [8192, 121]

    float* dHcat;
    cudaGetSymbolAddress((void**)&dHcat, g_hcat);

    static cudaStream_t s_side = []() {
        cudaStream_t s; cudaStreamCreateWithFlags(&s, cudaStreamNonBlocking); return s;
    }();
    static cudaEvent_t ev_fork = []() {
        cudaEvent_t e; cudaEventCreateWithFlags(&e, cudaEventDisableTiming); return e;
    }();
    static cudaEvent_t ev_join = []() {
        cudaEvent_t e; cudaEventCreateWithFlags(&e, cudaEventDisableTiming); return e;
    }();

    // fork: CSR build (DRAM-bound) runs concurrently with GEMM1 (FMA-bound)
    cudaEventRecord(ev_fork, 0);
    cudaStreamWaitEvent(s_side, ev_fork, 0);
    build_csr<<<N_NODES / 8, 256, 0, s_side>>>(adj);
    cudaEventRecord(ev_join, s_side);

    // main stream: layer-1 GEMM with fused f1 epilogue + fp16 Wh store
    sgemm6<0><<<dim3(4, N_NODES / 64), 256>>>(x, Ws, a_heads);

    // join: aggregation needs both CSR and scores
    cudaStreamWaitEvent(0, ev_join, 0);
    layer1_agg<<<N_NODES / 4, 256>>>();

    // layer 2: GEMM with fused f2-partials epilogue + fp16 Wh2 store, then aggregate
    sgemm6<1><<<dim3(2, N_NODES / 64), 256>>>(dHcat, W_out, a_out);
    layer2_agg<<<N_NODES / 4, 256>>>(out);
}